// round 12
// baseline (speedup 1.0000x reference)
#include <cuda_runtime.h>
#include <cuda_fp16.h>
#include <cstdint>

#define BB 4
#define SS 2048
#define DD 128
#define CC 128
#define NCH 16
#define LDH 136       // half stride for 128-col tiles (272B rows)
#define LD2 72        // half stride for 64-col tiles (144B rows)
#define NBLK 128

// ------------------- scratch (device globals; no allocs allowed) -------------------
__device__ __half g_phiK[BB*SS*DD];        // 2 MB
__device__ __half g_phiQ[BB*SS*DD];        // 2 MB
__device__ __half g_Vth [BB*SS*DD];        // 2 MB  V^T per chunk: [chunk][e][t]
__device__ float  g_ScTp[2][BB*NCH*DD*DD]; // 8 MB  partial chunk states (t-halves)
__device__ float  g_ncp [2][BB*NCH*DD];
__device__ __half g_MpTh[BB*NCH*DD*DD];    // 2 MB  exclusive prefix, half
__device__ float  g_Np  [BB*NCH*DD];
__device__ unsigned int g_bar[2];          // monotonic ticket barriers (replay-safe)

// ------------------- helpers -------------------
__device__ __forceinline__ uint32_t sptr(const void* p){
    return (uint32_t)__cvta_generic_to_shared(p);
}

__device__ __forceinline__ void grid_barrier(int idx){
    __syncthreads();
    if (threadIdx.x == 0) {
        __threadfence();
        unsigned int ticket = atomicAdd(&g_bar[idx], 1u);
        unsigned int target = (ticket / NBLK + 1u) * NBLK;
        while (atomicAdd(&g_bar[idx], 0u) < target) { __nanosleep(32); }
    }
    __syncthreads();
}

#define MMA16(d, a, b0v, b1v) \
    asm volatile("mma.sync.aligned.m16n8k16.row.col.f32.f16.f16.f32 " \
        "{%0,%1,%2,%3},{%4,%5,%6,%7},{%8,%9},{%0,%1,%2,%3};" \
        : "+f"(d[0]),"+f"(d[1]),"+f"(d[2]),"+f"(d[3]) \
        : "r"(a[0]),"r"(a[1]),"r"(a[2]),"r"(a[3]),"r"(b0v),"r"(b1v))

#define LDSMX4(r, addr) \
    asm volatile("ldmatrix.sync.aligned.m8n8.x4.shared.b16 {%0,%1,%2,%3},[%4];" \
        : "=r"((r)[0]),"=r"((r)[1]),"=r"((r)[2]),"=r"((r)[3]) : "r"(addr))

#define CP_ASYNC16(dst_u32, src_ptr) \
    asm volatile("cp.async.ca.shared.global [%0], [%1], 16;" :: "r"(dst_u32), "l"(src_ptr))
#define CP_COMMIT() asm volatile("cp.async.commit_group;")
#define CP_WAIT(n)  asm volatile("cp.async.wait_group %0;" :: "n"(n))

#define FRAG_OFFS() \
    const int rowA  = lane & 15;                            \
    const int kofA  = (lane >> 4) * 8;                      \
    const int rowB4 = (lane & 7) + ((lane >> 4) & 1) * 8;   \
    const int kofB4 = ((lane >> 3) & 1) * 8;                \
    const int er    = lane >> 2;                            \
    const int ec    = (lane & 3) * 2;

#define LOADA2_S(dst, u, r0, k0, LDX) { \
    LDSMX4(dst[0], (u) + (uint32_t)((((r0) + rowA)*(LDX) + (k0) + kofA) << 1)); \
    LDSMX4(dst[1], (u) + (uint32_t)((((r0) + 16 + rowA)*(LDX) + (k0) + kofA) << 1)); }

#define LOADB32_S(dst8, u, n0, k0, LDX) { \
    LDSMX4((dst8),     (u) + (uint32_t)((((n0) + rowB4)*(LDX) + (k0) + kofB4) << 1)); \
    LDSMX4((dst8) + 4, (u) + (uint32_t)((((n0) + 16 + rowB4)*(LDX) + (k0) + kofB4) << 1)); }

#define LOADB16_S(dst4, u, n0, k0, LDX) \
    LDSMX4((dst4), (u) + (uint32_t)((((n0) + rowB4)*(LDX) + (k0) + kofB4) << 1));

// pipelined GEMM, 32x32 warp tile (acc[2][4][4]), NK k-iters of 16
#define GEMM_PIPE_24(acc, uA_, rA0, uB_, nB0, LDX, NK) { \
    uint32_t a_[2][2][4]; uint32_t b_[2][8]; \
    LOADA2_S(a_[0], uA_, rA0, 0, LDX); LOADB32_S(b_[0], uB_, nB0, 0, LDX); \
    _Pragma("unroll") \
    for (int kk = 0; kk < (NK); ++kk) { \
        const int cur = kk & 1, nxt = cur ^ 1; \
        if (kk < (NK)-1) { LOADA2_S(a_[nxt], uA_, rA0, (kk+1)*16, LDX); LOADB32_S(b_[nxt], uB_, nB0, (kk+1)*16, LDX); } \
        _Pragma("unroll") \
        for (int mi = 0; mi < 2; ++mi) \
            _Pragma("unroll") \
            for (int ni = 0; ni < 4; ++ni) \
                MMA16(acc[mi][ni], a_[cur][mi], b_[cur][2*ni], b_[cur][2*ni+1]); \
    } }

// ============================================================================
// Fused persistent kernel: 128 blocks, 512 threads.
//   Phase 1: phi (stacked 64K+64Q rows) + partial chunk state  (per t-half)
//   [grid barrier]  + cp.async prefetch of output Q/K tiles
//   Phase 2: exclusive prefix over chunks (all threads)
//   [grid barrier]  + cp.async prefetch of Mp/V^T tiles
//   Phase 3: output (j-split halves)
// ============================================================================
__global__ void __launch_bounds__(512, 1)
fused_kernel(const float* __restrict__ K, const float* __restrict__ Q,
             const float* __restrict__ W, const float* __restrict__ V,
             float* __restrict__ out) {
    extern __shared__ char smraw[];
    const int tid  = threadIdx.x;
    const int lane = tid & 31;
    const int wid  = tid >> 5;
    const int chunk = blockIdx.x >> 1, half = blockIdx.x & 1;
    FRAG_OFFS();

    // ======================= PHASE 1 =======================
    {
        __half* Xs  = (__half*)smraw;              // [128][LDH]
        __half* Ws  = Xs + DD*LDH;                 // [128][LDH]
        __half* Kt2 = Ws + DD*LDH;                 // [128][LD2]
        __half* Vt2 = Kt2 + DD*LD2;                // [128][LD2]
        float*  scale = (float*)(Vt2 + DD*LD2);    // [128]

        const size_t rbase = (size_t)chunk*CC + half*64;
        const float* Kg = K + rbase*DD;
        const float* Qg = Q + rbase*DD;
        const float* Vg = V + rbase*DD;

        if (tid < 128) scale[tid] = 0.f;
        __syncthreads();

        #pragma unroll
        for (int it = 0; it < 8; ++it) {
            int i = tid + it*512;
            int t = i >> 5, d4 = i & 31;
            const float* src = (t < 64) ? (Kg + (size_t)t*DD) : (Qg + (size_t)(t-64)*DD);
            float4 v = reinterpret_cast<const float4*>(src)[d4];
            float ls = v.x*v.x + v.y*v.y + v.z*v.z + v.w*v.w;
            ls += __shfl_xor_sync(~0u, ls, 16);
            ls += __shfl_xor_sync(~0u, ls, 8);
            ls += __shfl_xor_sync(~0u, ls, 4);
            ls += __shfl_xor_sync(~0u, ls, 2);
            ls += __shfl_xor_sync(~0u, ls, 1);
            if (lane == 0) atomicAdd(&scale[t], ls);
            *reinterpret_cast<__half2*>(Xs + t*LDH + d4*4)     = __floats2half2_rn(v.x, v.y);
            *reinterpret_cast<__half2*>(Xs + t*LDH + d4*4 + 2) = __floats2half2_rn(v.z, v.w);
            float4 w = reinterpret_cast<const float4*>(W)[t*32 + d4];
            *reinterpret_cast<__half2*>(Ws + t*LDH + d4*4)     = __floats2half2_rn(w.x, w.y);
            *reinterpret_cast<__half2*>(Ws + t*LDH + d4*4 + 2) = __floats2half2_rn(w.z, w.w);
        }
        __syncthreads();
        if (tid < 128)
            scale[tid] = __expf(-0.5f * sqrtf(scale[tid])) * 0.08838834764831845f;

        float4 vreg[8];
        if (wid >= 8) {
            int q = tid - 256;
            #pragma unroll
            for (int it = 0; it < 8; ++it) {
                int i = q + it*256;
                vreg[it] = reinterpret_cast<const float4*>(Vg)[(size_t)(i & 63)*32 + (i >> 6)];
            }
        }
        __syncthreads();

        const int wm0 = (wid >> 2) * 32;
        const int wn0 = (wid & 3) * 32;
        const uint32_t uX = sptr(Xs), uW = sptr(Ws);
        const uint32_t uK2 = sptr(Kt2), uV2 = sptr(Vt2);

        float acc[2][4][4];
        #pragma unroll
        for (int mi = 0; mi < 2; ++mi)
            #pragma unroll
            for (int ni = 0; ni < 4; ++ni)
                #pragma unroll
                for (int q = 0; q < 4; ++q) acc[mi][ni][q] = 0.f;

        GEMM_PIPE_24(acc, uX, wm0, uW, wn0, LDH, 8);

        __half2 oph[2][4][2];
        #pragma unroll
        for (int mi = 0; mi < 2; ++mi) {
            int r0 = wm0 + mi*16 + er;
            float s0 = scale[r0], s1 = scale[r0 + 8];
            #pragma unroll
            for (int ni = 0; ni < 4; ++ni) {
                oph[mi][ni][0] = __floats2half2_rn(s0*__expf(acc[mi][ni][0]), s0*__expf(acc[mi][ni][1]));
                oph[mi][ni][1] = __floats2half2_rn(s1*__expf(acc[mi][ni][2]), s1*__expf(acc[mi][ni][3]));
            }
        }

        {
            __half* dst = (wm0 < 64) ? g_phiK : g_phiQ;
            int mofs    = (wm0 < 64) ? 0 : 64;
            #pragma unroll
            for (int mi = 0; mi < 2; ++mi) {
                int m = wm0 + mi*16 + er;
                size_t g0 = (rbase + (m - mofs)) * DD;
                #pragma unroll
                for (int ni = 0; ni < 4; ++ni) {
                    int col = wn0 + ni*8 + ec;
                    *reinterpret_cast<__half2*>(dst + g0 + col)        = oph[mi][ni][0];
                    *reinterpret_cast<__half2*>(dst + g0 + 8*DD + col) = oph[mi][ni][1];
                }
            }
        }

        if (wm0 < 64) {
            #pragma unroll
            for (int mi = 0; mi < 2; ++mi) {
                int t0 = wm0 + mi*16 + er;
                #pragma unroll
                for (int ni = 0; ni < 4; ++ni) {
                    int col = wn0 + ni*8 + ec;
                    Kt2[(col  )*LD2 + t0]     = oph[mi][ni][0].x;
                    Kt2[(col+1)*LD2 + t0]     = oph[mi][ni][0].y;
                    Kt2[(col  )*LD2 + t0 + 8] = oph[mi][ni][1].x;
                    Kt2[(col+1)*LD2 + t0 + 8] = oph[mi][ni][1].y;
                }
            }
        } else {
            __half* Vthg = g_Vth + (size_t)chunk*CC*DD + half*64;
            int q = tid - 256;
            #pragma unroll
            for (int it = 0; it < 8; ++it) {
                int i = q + it*256;
                int t = i & 63, d4 = i >> 6;
                float4 v = vreg[it];
                __half h0 = __float2half_rn(v.x), h1 = __float2half_rn(v.y);
                __half h2 = __float2half_rn(v.z), h3 = __float2half_rn(v.w);
                Vt2[(d4*4+0)*LD2 + t] = h0;
                Vt2[(d4*4+1)*LD2 + t] = h1;
                Vt2[(d4*4+2)*LD2 + t] = h2;
                Vt2[(d4*4+3)*LD2 + t] = h3;
                Vthg[(size_t)(d4*4+0)*128 + t] = h0;
                Vthg[(size_t)(d4*4+1)*128 + t] = h1;
                Vthg[(size_t)(d4*4+2)*128 + t] = h2;
                Vthg[(size_t)(d4*4+3)*128 + t] = h3;
            }
        }
        __syncthreads();

        float acc2[2][4][4];
        #pragma unroll
        for (int mi = 0; mi < 2; ++mi)
            #pragma unroll
            for (int ni = 0; ni < 4; ++ni)
                #pragma unroll
                for (int q = 0; q < 4; ++q) acc2[mi][ni][q] = 0.f;

        GEMM_PIPE_24(acc2, uV2, wm0, uK2, wn0, LD2, 4);

        float* Sg = g_ScTp[half] + (size_t)chunk*DD*DD;
        #pragma unroll
        for (int mi = 0; mi < 2; ++mi) {
            int r0 = wm0 + mi*16 + er;
            #pragma unroll
            for (int ni = 0; ni < 4; ++ni) {
                int col = wn0 + ni*8 + ec;
                *reinterpret_cast<float2*>(Sg + (size_t)r0*DD + col)     = make_float2(acc2[mi][ni][0], acc2[mi][ni][1]);
                *reinterpret_cast<float2*>(Sg + (size_t)(r0+8)*DD + col) = make_float2(acc2[mi][ni][2], acc2[mi][ni][3]);
            }
        }

        if (tid < 128) {
            float s = 0.f;
            #pragma unroll 8
            for (int t = 0; t < 64; ++t) s += __half2float(Kt2[tid*LD2 + t]);
            g_ncp[half][(size_t)chunk*DD + tid] = s;
        }
    }

    // ======= barrier 1: phi / ScTp / ncp / Vth globally visible =======
    grid_barrier(0);

    // phase-3 smem views (alias phase-1 regions, now dead)
    __half* Qs = (__half*)smraw;         // [128][LDH]
    __half* Bs = Qs + DD*LDH;            // [128][LDH]
    __half* As = Bs + DD*LDH;            // [128][LDH]
    __half* Ms = As + DD*LDH;            // [64][LDH]
    __half* Vs = Ms + 64*LDH;            // [64][LDH]
    float*  rs = (float*)(Vs + 64*LDH);  // [128]
    float*  Np = rs + 128;               // [128]
    const uint32_t uQ = sptr(Qs), uB = sptr(Bs), uA = sptr(As);
    const uint32_t uM = sptr(Ms), uV = sptr(Vs);

    const int h = half, j0h = h * 64;
    const __half* Qg3 = g_phiQ + (size_t)chunk*CC*DD;
    const __half* Kg3 = g_phiK + (size_t)chunk*CC*DD;
    const __half* Mg3 = g_MpTh + (size_t)chunk*DD*DD + (size_t)j0h*DD;
    const __half* Vg3 = g_Vth  + (size_t)chunk*CC*DD + (size_t)j0h*DD;

    // group 0: Q + K tiles (ready now) -- loads hide under the prefix phase
    #pragma unroll
    for (int it = 0; it < 4; ++it) {
        int i = tid + it*512;
        int t = i >> 4, c8 = i & 15;
        CP_ASYNC16(uQ + t*(LDH*2) + c8*16, Qg3 + t*128 + c8*8);
        CP_ASYNC16(uB + t*(LDH*2) + c8*16, Kg3 + t*128 + c8*8);
    }
    CP_COMMIT();

    // ======================= PHASE 2: prefix =======================
    {
        int gtid = blockIdx.x*512 + tid;          // 0..65535, one e-column each
        int bb = gtid >> 14;                      // batch
        int e0 = gtid & 16383;
        const size_t base = (size_t)bb*NCH*DD*DD + e0;
        float a = 0.f;
        #pragma unroll 4
        for (int c = 0; c < NCH; ++c) {
            size_t off = base + (size_t)c*DD*DD;
            g_MpTh[off] = __float2half_rn(a);
            a += g_ScTp[0][off] + g_ScTp[1][off];
        }
        if (gtid < 512) {
            int b2 = gtid >> 7, i2 = gtid & 127;
            float an = 0.f;
            for (int c = 0; c < NCH; ++c) {
                size_t off = (size_t)(b2*NCH + c)*DD + i2;
                g_Np[off] = an;
                an += g_ncp[0][off] + g_ncp[1][off];
            }
        }
    }

    // ======= barrier 2: MpTh / Np globally visible =======
    grid_barrier(1);

    // group 1: Mp + V^T tiles
    #pragma unroll
    for (int it = 0; it < 2; ++it) {
        int i = tid + it*512;
        int e = i >> 4, c8 = i & 15;
        CP_ASYNC16(uM + e*(LDH*2) + c8*16, Mg3 + e*128 + c8*8);
        CP_ASYNC16(uV + e*(LDH*2) + c8*16, Vg3 + e*128 + c8*8);
    }
    CP_COMMIT();

    if (tid < 128) {
        rs[tid] = 0.f;
        Np[tid] = g_Np[(size_t)chunk*DD + tid];
    }
    CP_WAIT(1);          // Q/K resident
    __syncthreads();

    // ======================= PHASE 3: output =======================
    const int wm0 = (wid >> 2) * 32;

    // ---- Phase A ----
    {
        const int wn0 = (wid & 3) * 32;
        float acc[2][4][4];
        #pragma unroll
        for (int mi = 0; mi < 2; ++mi)
            #pragma unroll
            for (int ni = 0; ni < 4; ++ni)
                #pragma unroll
                for (int q = 0; q < 4; ++q) acc[mi][ni][q] = 0.f;

        GEMM_PIPE_24(acc, uQ, wm0, uB, wn0, LDH, 8);

        #pragma unroll
        for (int mi = 0; mi < 2; ++mi) {
            int t0 = wm0 + mi*16 + er;
            int t1 = t0 + 8;
            #pragma unroll
            for (int ni = 0; ni < 4; ++ni) {
                int s0 = wn0 + ni*8 + ec;
                float v0 = (s0     <= t0) ? acc[mi][ni][0] : 0.f;
                float v1 = (s0 + 1 <= t0) ? acc[mi][ni][1] : 0.f;
                float v2 = (s0     <= t1) ? acc[mi][ni][2] : 0.f;
                float v3 = (s0 + 1 <= t1) ? acc[mi][ni][3] : 0.f;
                *reinterpret_cast<__half2*>(As + t0*LDH + s0) = __floats2half2_rn(v0, v1);
                *reinterpret_cast<__half2*>(As + t1*LDH + s0) = __floats2half2_rn(v2, v3);
            }
        }
    }
    __syncthreads();

    // ---- denominators ----
    {
        int t = tid & 127, p = tid >> 7;
        float r = 0.f;
        const int s0 = p * 32;
        #pragma unroll 8
        for (int s = s0; s < s0 + 32; s += 2) {
            float2 f = __half22float2(*reinterpret_cast<__half2*>(As + t*LDH + s));
            r += f.x + f.y;
        }
        #pragma unroll 8
        for (int d = s0; d < s0 + 32; ++d)
            r = fmaf(__half2float(Qs[t*LDH + d]), Np[d], r);
        atomicAdd(&rs[t], r);
    }
    CP_WAIT(0);          // Mp/V resident
    __syncthreads();

    // ---- Phase B+C ----
    {
        const int wn0 = (wid & 3) * 16;
        float acc[2][2][4];
        #pragma unroll
        for (int mi = 0; mi < 2; ++mi)
            #pragma unroll
            for (int ni = 0; ni < 2; ++ni)
                #pragma unroll
                for (int q = 0; q < 4; ++q) acc[mi][ni][q] = 0.f;

        uint32_t a_[2][2][4]; uint32_t b_[2][4];
        LOADA2_S(a_[0], uQ, wm0, 0, LDH);
        LOADB16_S(b_[0], uM, wn0, 0, LDH);
        #pragma unroll
        for (int kk = 0; kk < 16; ++kk) {
            const int cur = kk & 1, nxt = cur ^ 1;
            const int k1 = kk + 1;
            if (k1 < 8) {
                LOADA2_S(a_[nxt], uQ, wm0, k1*16, LDH);
                LOADB16_S(b_[nxt], uM, wn0, k1*16, LDH);
            } else if (k1 < 16) {
                LOADA2_S(a_[nxt], uA, wm0, (k1-8)*16, LDH);
                LOADB16_S(b_[nxt], uV, wn0, (k1-8)*16, LDH);
            }
            #pragma unroll
            for (int mi = 0; mi < 2; ++mi)
                #pragma unroll
                for (int ni = 0; ni < 2; ++ni)
                    MMA16(acc[mi][ni], a_[cur][mi], b_[cur][2*ni], b_[cur][2*ni+1]);
        }

        #pragma unroll
        for (int mi = 0; mi < 2; ++mi) {
            int t0 = wm0 + mi*16 + er;
            float r0 = rs[t0];
            float inv0 = 1.f / (r0 + (r0 > 0.f ? 1e-6f : (r0 < 0.f ? -1e-6f : 0.f)));
            float r1 = rs[t0 + 8];
            float inv1 = 1.f / (r1 + (r1 > 0.f ? 1e-6f : (r1 < 0.f ? -1e-6f : 0.f)));
            size_t row0 = (size_t)chunk*CC + t0;
            #pragma unroll
            for (int ni = 0; ni < 2; ++ni) {
                int col = j0h + wn0 + ni*8 + ec;
                *reinterpret_cast<float2*>(out + row0*DD + col) =
                    make_float2(acc[mi][ni][0]*inv0, acc[mi][ni][1]*inv0);
                *reinterpret_cast<float2*>(out + (row0 + 8)*DD + col) =
                    make_float2(acc[mi][ni][2]*inv1, acc[mi][ni][3]*inv1);
            }
        }
    }
}

// ============================================================================
extern "C" void kernel_launch(void* const* d_in, const int* in_sizes, int n_in,
                              void* d_out, int out_size) {
    const float* K = (const float*)d_in[0];
    const float* Q = (const float*)d_in[1];
    const float* V = (const float*)d_in[2];
    const float* W = (const float*)d_in[6];
    float* out = (float*)d_out;

    // max(phase1, phase3) smem: phase3 = (3*128 + 2*64)*LDH halfs + 1024 B
    const int SMEM = (3*DD + 2*64)*LDH*2 + 1024;   // ~141 KB

    cudaFuncSetAttribute(fused_kernel, cudaFuncAttributeMaxDynamicSharedMemorySize, SMEM);
    fused_kernel<<<NBLK, 512, SMEM>>>(K, Q, W, V, out);
}

// round 13
// speedup vs baseline: 1.0267x; 1.0267x over previous
#include <cuda_runtime.h>
#include <cuda_fp16.h>
#include <cstdint>

#define BB 4
#define SS 2048
#define DD 128
#define CC 128
#define NCH 16
#define LDH 136       // half stride for 128-col tiles (272B rows)
#define LD2 72        // half stride for 64-col tiles (144B rows)
#define NBLK 128

// ------------------- scratch (device globals; no allocs allowed) -------------------
__device__ __half g_phiK[BB*SS*DD];        // 2 MB
__device__ __half g_phiQ[BB*SS*DD];        // 2 MB
__device__ __half g_Vth [BB*SS*DD];        // 2 MB  V^T per chunk: [chunk][e][t]
__device__ float  g_ScTp[2][BB*NCH*DD*DD]; // 8 MB  partial chunk states (t-halves)
__device__ float  g_ncp [2][BB*NCH*DD];
__device__ __half g_MpTh[BB*NCH*DD*DD];    // 2 MB  exclusive prefix, half
__device__ float  g_Np  [BB*NCH*DD];
__device__ unsigned int g_bar[2];          // monotonic ticket barriers (replay-safe)

// ------------------- helpers -------------------
__device__ __forceinline__ uint32_t sptr(const void* p){
    return (uint32_t)__cvta_generic_to_shared(p);
}

// release-arrive / acquire-poll grid barrier (no atomic-RMW polling, no L1 flush)
__device__ __forceinline__ void grid_barrier(int idx){
    __syncthreads();
    if (threadIdx.x == 0) {
        unsigned int ticket;
        asm volatile("atom.release.gpu.global.add.u32 %0, [%1], 1;"
                     : "=r"(ticket) : "l"(&g_bar[idx]) : "memory");
        unsigned int target = (ticket / NBLK + 1u) * NBLK;
        unsigned int cur;
        do {
            asm volatile("ld.acquire.gpu.global.u32 %0, [%1];"
                         : "=r"(cur) : "l"(&g_bar[idx]) : "memory");
        } while (cur < target);
    }
    __syncthreads();
}

#define MMA16(d, a, b0v, b1v) \
    asm volatile("mma.sync.aligned.m16n8k16.row.col.f32.f16.f16.f32 " \
        "{%0,%1,%2,%3},{%4,%5,%6,%7},{%8,%9},{%0,%1,%2,%3};" \
        : "+f"(d[0]),"+f"(d[1]),"+f"(d[2]),"+f"(d[3]) \
        : "r"(a[0]),"r"(a[1]),"r"(a[2]),"r"(a[3]),"r"(b0v),"r"(b1v))

#define LDSMX4(r, addr) \
    asm volatile("ldmatrix.sync.aligned.m8n8.x4.shared.b16 {%0,%1,%2,%3},[%4];" \
        : "=r"((r)[0]),"=r"((r)[1]),"=r"((r)[2]),"=r"((r)[3]) : "r"(addr))

#define CP_ASYNC16(dst_u32, src_ptr) \
    asm volatile("cp.async.ca.shared.global [%0], [%1], 16;" :: "r"(dst_u32), "l"(src_ptr))
#define CP_COMMIT() asm volatile("cp.async.commit_group;")
#define CP_WAIT(n)  asm volatile("cp.async.wait_group %0;" :: "n"(n))

#define FRAG_OFFS() \
    const int rowA  = lane & 15;                            \
    const int kofA  = (lane >> 4) * 8;                      \
    const int rowB4 = (lane & 7) + ((lane >> 4) & 1) * 8;   \
    const int kofB4 = ((lane >> 3) & 1) * 8;                \
    const int er    = lane >> 2;                            \
    const int ec    = (lane & 3) * 2;

#define LOADA2_S(dst, u, r0, k0, LDX) { \
    LDSMX4(dst[0], (u) + (uint32_t)((((r0) + rowA)*(LDX) + (k0) + kofA) << 1)); \
    LDSMX4(dst[1], (u) + (uint32_t)((((r0) + 16 + rowA)*(LDX) + (k0) + kofA) << 1)); }

#define LOADB32_S(dst8, u, n0, k0, LDX) { \
    LDSMX4((dst8),     (u) + (uint32_t)((((n0) + rowB4)*(LDX) + (k0) + kofB4) << 1)); \
    LDSMX4((dst8) + 4, (u) + (uint32_t)((((n0) + 16 + rowB4)*(LDX) + (k0) + kofB4) << 1)); }

#define LOADB16_S(dst4, u, n0, k0, LDX) \
    LDSMX4((dst4), (u) + (uint32_t)((((n0) + rowB4)*(LDX) + (k0) + kofB4) << 1));

// pipelined GEMM, 32x32 warp tile (acc[2][4][4]), NK k-iters of 16
#define GEMM_PIPE_24(acc, uA_, rA0, uB_, nB0, LDX, NK) { \
    uint32_t a_[2][2][4]; uint32_t b_[2][8]; \
    LOADA2_S(a_[0], uA_, rA0, 0, LDX); LOADB32_S(b_[0], uB_, nB0, 0, LDX); \
    _Pragma("unroll") \
    for (int kk = 0; kk < (NK); ++kk) { \
        const int cur = kk & 1, nxt = cur ^ 1; \
        if (kk < (NK)-1) { LOADA2_S(a_[nxt], uA_, rA0, (kk+1)*16, LDX); LOADB32_S(b_[nxt], uB_, nB0, (kk+1)*16, LDX); } \
        _Pragma("unroll") \
        for (int mi = 0; mi < 2; ++mi) \
            _Pragma("unroll") \
            for (int ni = 0; ni < 4; ++ni) \
                MMA16(acc[mi][ni], a_[cur][mi], b_[cur][2*ni], b_[cur][2*ni+1]); \
    } }

// ============================================================================
// Fused persistent kernel: 128 blocks, 512 threads.
//   Phase 1: phi (stacked 64K+64Q rows) + partial chunk state  (per t-half)
//   [grid barrier]  + cp.async prefetch of output Q/K tiles
//   Phase 2: exclusive prefix over chunks (all threads)
//   [grid barrier]  + cp.async prefetch of Mp/V^T tiles
//   Phase 3: output (j-split halves)
// ============================================================================
__global__ void __launch_bounds__(512, 1)
fused_kernel(const float* __restrict__ K, const float* __restrict__ Q,
             const float* __restrict__ W, const float* __restrict__ V,
             float* __restrict__ out) {
    extern __shared__ char smraw[];
    const int tid  = threadIdx.x;
    const int lane = tid & 31;
    const int wid  = tid >> 5;
    const int chunk = blockIdx.x >> 1, half = blockIdx.x & 1;
    FRAG_OFFS();

    // ======================= PHASE 1 =======================
    {
        __half* Xs  = (__half*)smraw;              // [128][LDH]
        __half* Ws  = Xs + DD*LDH;                 // [128][LDH]
        __half* Kt2 = Ws + DD*LDH;                 // [128][LD2]
        __half* Vt2 = Kt2 + DD*LD2;                // [128][LD2]
        float*  scale = (float*)(Vt2 + DD*LD2);    // [128]

        const size_t rbase = (size_t)chunk*CC + half*64;
        const float* Kg = K + rbase*DD;
        const float* Qg = Q + rbase*DD;
        const float* Vg = V + rbase*DD;

        if (tid < 128) scale[tid] = 0.f;
        __syncthreads();

        #pragma unroll
        for (int it = 0; it < 8; ++it) {
            int i = tid + it*512;
            int t = i >> 5, d4 = i & 31;
            const float* src = (t < 64) ? (Kg + (size_t)t*DD) : (Qg + (size_t)(t-64)*DD);
            float4 v = reinterpret_cast<const float4*>(src)[d4];
            float ls = v.x*v.x + v.y*v.y + v.z*v.z + v.w*v.w;
            ls += __shfl_xor_sync(~0u, ls, 16);
            ls += __shfl_xor_sync(~0u, ls, 8);
            ls += __shfl_xor_sync(~0u, ls, 4);
            ls += __shfl_xor_sync(~0u, ls, 2);
            ls += __shfl_xor_sync(~0u, ls, 1);
            if (lane == 0) atomicAdd(&scale[t], ls);
            *reinterpret_cast<__half2*>(Xs + t*LDH + d4*4)     = __floats2half2_rn(v.x, v.y);
            *reinterpret_cast<__half2*>(Xs + t*LDH + d4*4 + 2) = __floats2half2_rn(v.z, v.w);
            float4 w = reinterpret_cast<const float4*>(W)[t*32 + d4];
            *reinterpret_cast<__half2*>(Ws + t*LDH + d4*4)     = __floats2half2_rn(w.x, w.y);
            *reinterpret_cast<__half2*>(Ws + t*LDH + d4*4 + 2) = __floats2half2_rn(w.z, w.w);
        }
        __syncthreads();
        if (tid < 128)
            scale[tid] = __expf(-0.5f * sqrtf(scale[tid])) * 0.08838834764831845f;

        float4 vreg[8];
        if (wid >= 8) {
            int q = tid - 256;
            #pragma unroll
            for (int it = 0; it < 8; ++it) {
                int i = q + it*256;
                vreg[it] = reinterpret_cast<const float4*>(Vg)[(size_t)(i & 63)*32 + (i >> 6)];
            }
        }
        __syncthreads();

        const int wm0 = (wid >> 2) * 32;
        const int wn0 = (wid & 3) * 32;
        const uint32_t uX = sptr(Xs), uW = sptr(Ws);
        const uint32_t uK2 = sptr(Kt2), uV2 = sptr(Vt2);

        float acc[2][4][4];
        #pragma unroll
        for (int mi = 0; mi < 2; ++mi)
            #pragma unroll
            for (int ni = 0; ni < 4; ++ni)
                #pragma unroll
                for (int q = 0; q < 4; ++q) acc[mi][ni][q] = 0.f;

        GEMM_PIPE_24(acc, uX, wm0, uW, wn0, LDH, 8);

        __half2 oph[2][4][2];
        #pragma unroll
        for (int mi = 0; mi < 2; ++mi) {
            int r0 = wm0 + mi*16 + er;
            float s0 = scale[r0], s1 = scale[r0 + 8];
            #pragma unroll
            for (int ni = 0; ni < 4; ++ni) {
                oph[mi][ni][0] = __floats2half2_rn(s0*__expf(acc[mi][ni][0]), s0*__expf(acc[mi][ni][1]));
                oph[mi][ni][1] = __floats2half2_rn(s1*__expf(acc[mi][ni][2]), s1*__expf(acc[mi][ni][3]));
            }
        }

        {
            __half* dst = (wm0 < 64) ? g_phiK : g_phiQ;
            int mofs    = (wm0 < 64) ? 0 : 64;
            #pragma unroll
            for (int mi = 0; mi < 2; ++mi) {
                int m = wm0 + mi*16 + er;
                size_t g0 = (rbase + (m - mofs)) * DD;
                #pragma unroll
                for (int ni = 0; ni < 4; ++ni) {
                    int col = wn0 + ni*8 + ec;
                    *reinterpret_cast<__half2*>(dst + g0 + col)        = oph[mi][ni][0];
                    *reinterpret_cast<__half2*>(dst + g0 + 8*DD + col) = oph[mi][ni][1];
                }
            }
        }

        if (wm0 < 64) {
            #pragma unroll
            for (int mi = 0; mi < 2; ++mi) {
                int t0 = wm0 + mi*16 + er;
                #pragma unroll
                for (int ni = 0; ni < 4; ++ni) {
                    int col = wn0 + ni*8 + ec;
                    Kt2[(col  )*LD2 + t0]     = oph[mi][ni][0].x;
                    Kt2[(col+1)*LD2 + t0]     = oph[mi][ni][0].y;
                    Kt2[(col  )*LD2 + t0 + 8] = oph[mi][ni][1].x;
                    Kt2[(col+1)*LD2 + t0 + 8] = oph[mi][ni][1].y;
                }
            }
        } else {
            __half* Vthg = g_Vth + (size_t)chunk*CC*DD + half*64;
            int q = tid - 256;
            #pragma unroll
            for (int it = 0; it < 8; ++it) {
                int i = q + it*256;
                int t = i & 63, d4 = i >> 6;
                float4 v = vreg[it];
                __half h0 = __float2half_rn(v.x), h1 = __float2half_rn(v.y);
                __half h2 = __float2half_rn(v.z), h3 = __float2half_rn(v.w);
                Vt2[(d4*4+0)*LD2 + t] = h0;
                Vt2[(d4*4+1)*LD2 + t] = h1;
                Vt2[(d4*4+2)*LD2 + t] = h2;
                Vt2[(d4*4+3)*LD2 + t] = h3;
                Vthg[(size_t)(d4*4+0)*128 + t] = h0;
                Vthg[(size_t)(d4*4+1)*128 + t] = h1;
                Vthg[(size_t)(d4*4+2)*128 + t] = h2;
                Vthg[(size_t)(d4*4+3)*128 + t] = h3;
            }
        }
        __syncthreads();

        float acc2[2][4][4];
        #pragma unroll
        for (int mi = 0; mi < 2; ++mi)
            #pragma unroll
            for (int ni = 0; ni < 4; ++ni)
                #pragma unroll
                for (int q = 0; q < 4; ++q) acc2[mi][ni][q] = 0.f;

        GEMM_PIPE_24(acc2, uV2, wm0, uK2, wn0, LD2, 4);

        float* Sg = g_ScTp[half] + (size_t)chunk*DD*DD;
        #pragma unroll
        for (int mi = 0; mi < 2; ++mi) {
            int r0 = wm0 + mi*16 + er;
            #pragma unroll
            for (int ni = 0; ni < 4; ++ni) {
                int col = wn0 + ni*8 + ec;
                *reinterpret_cast<float2*>(Sg + (size_t)r0*DD + col)     = make_float2(acc2[mi][ni][0], acc2[mi][ni][1]);
                *reinterpret_cast<float2*>(Sg + (size_t)(r0+8)*DD + col) = make_float2(acc2[mi][ni][2], acc2[mi][ni][3]);
            }
        }

        if (tid < 128) {
            float s = 0.f;
            #pragma unroll 8
            for (int t = 0; t < 64; ++t) s += __half2float(Kt2[tid*LD2 + t]);
            g_ncp[half][(size_t)chunk*DD + tid] = s;
        }
    }

    // ======= barrier 1: phi / ScTp / ncp / Vth globally visible =======
    grid_barrier(0);

    // phase-3 smem views (alias phase-1 regions, now dead)
    __half* Qs = (__half*)smraw;         // [128][LDH]
    __half* Bs = Qs + DD*LDH;            // [128][LDH]
    __half* As = Bs + DD*LDH;            // [128][LDH]
    __half* Ms = As + DD*LDH;            // [64][LDH]
    __half* Vs = Ms + 64*LDH;            // [64][LDH]
    float*  rs = (float*)(Vs + 64*LDH);  // [128]
    float*  Np = rs + 128;               // [128]
    const uint32_t uQ = sptr(Qs), uB = sptr(Bs), uA = sptr(As);
    const uint32_t uM = sptr(Ms), uV = sptr(Vs);

    const int h = half, j0h = h * 64;
    const __half* Qg3 = g_phiQ + (size_t)chunk*CC*DD;
    const __half* Kg3 = g_phiK + (size_t)chunk*CC*DD;
    const __half* Mg3 = g_MpTh + (size_t)chunk*DD*DD + (size_t)j0h*DD;
    const __half* Vg3 = g_Vth  + (size_t)chunk*CC*DD + (size_t)j0h*DD;

    // group 0: Q + K tiles (ready now) -- loads hide under the prefix phase
    #pragma unroll
    for (int it = 0; it < 4; ++it) {
        int i = tid + it*512;
        int t = i >> 4, c8 = i & 15;
        CP_ASYNC16(uQ + t*(LDH*2) + c8*16, Qg3 + t*128 + c8*8);
        CP_ASYNC16(uB + t*(LDH*2) + c8*16, Kg3 + t*128 + c8*8);
    }
    CP_COMMIT();

    // ======================= PHASE 2: prefix =======================
    {
        int gtid = blockIdx.x*512 + tid;          // 0..65535, one e-column each
        int bb = gtid >> 14;                      // batch
        int e0 = gtid & 16383;
        const size_t base = (size_t)bb*NCH*DD*DD + e0;
        float a = 0.f;
        #pragma unroll
        for (int c = 0; c < NCH; ++c) {
            size_t off = base + (size_t)c*DD*DD;
            g_MpTh[off] = __float2half_rn(a);
            a += g_ScTp[0][off] + g_ScTp[1][off];
        }
        if (gtid < 512) {
            int b2 = gtid >> 7, i2 = gtid & 127;
            float an = 0.f;
            #pragma unroll
            for (int c = 0; c < NCH; ++c) {
                size_t off = (size_t)(b2*NCH + c)*DD + i2;
                g_Np[off] = an;
                an += g_ncp[0][off] + g_ncp[1][off];
            }
        }
    }

    // ======= barrier 2: MpTh / Np globally visible =======
    grid_barrier(1);

    // group 1: Mp + V^T tiles
    #pragma unroll
    for (int it = 0; it < 2; ++it) {
        int i = tid + it*512;
        int e = i >> 4, c8 = i & 15;
        CP_ASYNC16(uM + e*(LDH*2) + c8*16, Mg3 + e*128 + c8*8);
        CP_ASYNC16(uV + e*(LDH*2) + c8*16, Vg3 + e*128 + c8*8);
    }
    CP_COMMIT();

    if (tid < 128) {
        rs[tid] = 0.f;
        Np[tid] = g_Np[(size_t)chunk*DD + tid];
    }
    CP_WAIT(1);          // Q/K resident
    __syncthreads();

    // ======================= PHASE 3: output =======================
    const int wm0 = (wid >> 2) * 32;

    // ---- Phase A ----
    {
        const int wn0 = (wid & 3) * 32;
        float acc[2][4][4];
        #pragma unroll
        for (int mi = 0; mi < 2; ++mi)
            #pragma unroll
            for (int ni = 0; ni < 4; ++ni)
                #pragma unroll
                for (int q = 0; q < 4; ++q) acc[mi][ni][q] = 0.f;

        GEMM_PIPE_24(acc, uQ, wm0, uB, wn0, LDH, 8);

        #pragma unroll
        for (int mi = 0; mi < 2; ++mi) {
            int t0 = wm0 + mi*16 + er;
            int t1 = t0 + 8;
            #pragma unroll
            for (int ni = 0; ni < 4; ++ni) {
                int s0 = wn0 + ni*8 + ec;
                float v0 = (s0     <= t0) ? acc[mi][ni][0] : 0.f;
                float v1 = (s0 + 1 <= t0) ? acc[mi][ni][1] : 0.f;
                float v2 = (s0     <= t1) ? acc[mi][ni][2] : 0.f;
                float v3 = (s0 + 1 <= t1) ? acc[mi][ni][3] : 0.f;
                *reinterpret_cast<__half2*>(As + t0*LDH + s0) = __floats2half2_rn(v0, v1);
                *reinterpret_cast<__half2*>(As + t1*LDH + s0) = __floats2half2_rn(v2, v3);
            }
        }
    }
    __syncthreads();

    // ---- denominators ----
    {
        int t = tid & 127, p = tid >> 7;
        float r = 0.f;
        const int s0 = p * 32;
        #pragma unroll 8
        for (int s = s0; s < s0 + 32; s += 2) {
            float2 f = __half22float2(*reinterpret_cast<__half2*>(As + t*LDH + s));
            r += f.x + f.y;
        }
        #pragma unroll 8
        for (int d = s0; d < s0 + 32; ++d)
            r = fmaf(__half2float(Qs[t*LDH + d]), Np[d], r);
        atomicAdd(&rs[t], r);
    }
    CP_WAIT(0);          // Mp/V resident
    __syncthreads();

    // ---- Phase B+C ----
    {
        const int wn0 = (wid & 3) * 16;
        float acc[2][2][4];
        #pragma unroll
        for (int mi = 0; mi < 2; ++mi)
            #pragma unroll
            for (int ni = 0; ni < 2; ++ni)
                #pragma unroll
                for (int q = 0; q < 4; ++q) acc[mi][ni][q] = 0.f;

        uint32_t a_[2][2][4]; uint32_t b_[2][4];
        LOADA2_S(a_[0], uQ, wm0, 0, LDH);
        LOADB16_S(b_[0], uM, wn0, 0, LDH);
        #pragma unroll
        for (int kk = 0; kk < 16; ++kk) {
            const int cur = kk & 1, nxt = cur ^ 1;
            const int k1 = kk + 1;
            if (k1 < 8) {
                LOADA2_S(a_[nxt], uQ, wm0, k1*16, LDH);
                LOADB16_S(b_[nxt], uM, wn0, k1*16, LDH);
            } else if (k1 < 16) {
                LOADA2_S(a_[nxt], uA, wm0, (k1-8)*16, LDH);
                LOADB16_S(b_[nxt], uV, wn0, (k1-8)*16, LDH);
            }
            #pragma unroll
            for (int mi = 0; mi < 2; ++mi)
                #pragma unroll
                for (int ni = 0; ni < 2; ++ni)
                    MMA16(acc[mi][ni], a_[cur][mi], b_[cur][2*ni], b_[cur][2*ni+1]);
        }

        #pragma unroll
        for (int mi = 0; mi < 2; ++mi) {
            int t0 = wm0 + mi*16 + er;
            float r0 = rs[t0];
            float inv0 = 1.f / (r0 + (r0 > 0.f ? 1e-6f : (r0 < 0.f ? -1e-6f : 0.f)));
            float r1 = rs[t0 + 8];
            float inv1 = 1.f / (r1 + (r1 > 0.f ? 1e-6f : (r1 < 0.f ? -1e-6f : 0.f)));
            size_t row0 = (size_t)chunk*CC + t0;
            #pragma unroll
            for (int ni = 0; ni < 2; ++ni) {
                int col = j0h + wn0 + ni*8 + ec;
                *reinterpret_cast<float2*>(out + row0*DD + col) =
                    make_float2(acc[mi][ni][0]*inv0, acc[mi][ni][1]*inv0);
                *reinterpret_cast<float2*>(out + (row0 + 8)*DD + col) =
                    make_float2(acc[mi][ni][2]*inv1, acc[mi][ni][3]*inv1);
            }
        }
    }
}

// ============================================================================
extern "C" void kernel_launch(void* const* d_in, const int* in_sizes, int n_in,
                              void* d_out, int out_size) {
    const float* K = (const float*)d_in[0];
    const float* Q = (const float*)d_in[1];
    const float* V = (const float*)d_in[2];
    const float* W = (const float*)d_in[6];
    float* out = (float*)d_out;

    const int SMEM = (3*DD + 2*64)*LDH*2 + 1024;   // ~141 KB

    cudaFuncSetAttribute(fused_kernel, cudaFuncAttributeMaxDynamicSharedMemorySize, SMEM);
    fused_kernel<<<NBLK, 512, SMEM>>>(K, Q, W, V, out);
}

// round 14
// speedup vs baseline: 1.0571x; 1.0297x over previous
#include <cuda_runtime.h>
#include <cuda_fp16.h>
#include <cstdint>

#define BB 4
#define SS 2048
#define DD 128
#define CC 128
#define NCH 16
#define LDH 136       // half stride for 128-col tiles (272B rows)
#define LD2 72        // half stride for 64-col tiles (144B rows)
#define NBLK 128

// ------------------- scratch (device globals; no allocs allowed) -------------------
__device__ __half g_phiK[BB*SS*DD];        // 2 MB
__device__ __half g_phiQ[BB*SS*DD];        // 2 MB
__device__ __half g_Vth [BB*SS*DD];        // 2 MB  V^T per chunk: [chunk][e][t]
__device__ float  g_ScTp[2][BB*NCH*DD*DD]; // 8 MB  partial chunk states (t-halves)
__device__ float  g_ncp [2][BB*NCH*DD];
__device__ __half g_MpTh[BB*NCH*DD*DD];    // 2 MB  exclusive prefix, half
__device__ float  g_Np  [BB*NCH*DD];
__device__ unsigned int g_bar[2];          // monotonic ticket barriers (replay-safe)
__device__ unsigned int g_pair[64];        // per-chunk pairwise barriers

// ------------------- helpers -------------------
__device__ __forceinline__ uint32_t sptr(const void* p){
    return (uint32_t)__cvta_generic_to_shared(p);
}

__device__ __forceinline__ unsigned int bar_arrive(unsigned int* addr, unsigned int n){
    unsigned int ticket;
    asm volatile("atom.release.gpu.global.add.u32 %0, [%1], 1;"
                 : "=r"(ticket) : "l"(addr) : "memory");
    return (ticket / n + 1u) * n;          // target value
}
__device__ __forceinline__ void bar_wait(unsigned int* addr, unsigned int target){
    unsigned int cur;
    do {
        asm volatile("ld.acquire.gpu.global.u32 %0, [%1];"
                     : "=r"(cur) : "l"(addr) : "memory");
    } while (cur < target);
}

#define MMA16(d, a, b0v, b1v) \
    asm volatile("mma.sync.aligned.m16n8k16.row.col.f32.f16.f16.f32 " \
        "{%0,%1,%2,%3},{%4,%5,%6,%7},{%8,%9},{%0,%1,%2,%3};" \
        : "+f"(d[0]),"+f"(d[1]),"+f"(d[2]),"+f"(d[3]) \
        : "r"(a[0]),"r"(a[1]),"r"(a[2]),"r"(a[3]),"r"(b0v),"r"(b1v))

#define LDSMX4(r, addr) \
    asm volatile("ldmatrix.sync.aligned.m8n8.x4.shared.b16 {%0,%1,%2,%3},[%4];" \
        : "=r"((r)[0]),"=r"((r)[1]),"=r"((r)[2]),"=r"((r)[3]) : "r"(addr))

#define CP_ASYNC16(dst_u32, src_ptr) \
    asm volatile("cp.async.ca.shared.global [%0], [%1], 16;" :: "r"(dst_u32), "l"(src_ptr))
#define CP_COMMIT() asm volatile("cp.async.commit_group;")
#define CP_WAIT(n)  asm volatile("cp.async.wait_group %0;" :: "n"(n))

#define FRAG_OFFS() \
    const int rowA  = lane & 15;                            \
    const int kofA  = (lane >> 4) * 8;                      \
    const int rowB4 = (lane & 7) + ((lane >> 4) & 1) * 8;   \
    const int kofB4 = ((lane >> 3) & 1) * 8;                \
    const int er    = lane >> 2;                            \
    const int ec    = (lane & 3) * 2;

#define LOADA2_S(dst, u, r0, k0, LDX) { \
    LDSMX4(dst[0], (u) + (uint32_t)((((r0) + rowA)*(LDX) + (k0) + kofA) << 1)); \
    LDSMX4(dst[1], (u) + (uint32_t)((((r0) + 16 + rowA)*(LDX) + (k0) + kofA) << 1)); }

#define LOADB32_S(dst8, u, n0, k0, LDX) { \
    LDSMX4((dst8),     (u) + (uint32_t)((((n0) + rowB4)*(LDX) + (k0) + kofB4) << 1)); \
    LDSMX4((dst8) + 4, (u) + (uint32_t)((((n0) + 16 + rowB4)*(LDX) + (k0) + kofB4) << 1)); }

#define LOADB16_S(dst4, u, n0, k0, LDX) \
    LDSMX4((dst4), (u) + (uint32_t)((((n0) + rowB4)*(LDX) + (k0) + kofB4) << 1));

// pipelined GEMM, 32x32 warp tile (acc[2][4][4]), NK k-iters of 16
#define GEMM_PIPE_24(acc, uA_, rA0, uB_, nB0, LDX, NK) { \
    uint32_t a_[2][2][4]; uint32_t b_[2][8]; \
    LOADA2_S(a_[0], uA_, rA0, 0, LDX); LOADB32_S(b_[0], uB_, nB0, 0, LDX); \
    _Pragma("unroll") \
    for (int kk = 0; kk < (NK); ++kk) { \
        const int cur = kk & 1, nxt = cur ^ 1; \
        if (kk < (NK)-1) { LOADA2_S(a_[nxt], uA_, rA0, (kk+1)*16, LDX); LOADB32_S(b_[nxt], uB_, nB0, (kk+1)*16, LDX); } \
        _Pragma("unroll") \
        for (int mi = 0; mi < 2; ++mi) \
            _Pragma("unroll") \
            for (int ni = 0; ni < 4; ++ni) \
                MMA16(acc[mi][ni], a_[cur][mi], b_[cur][2*ni], b_[cur][2*ni+1]); \
    } }

// ============================================================================
// Fused persistent kernel, deferred-wait scheduling:
//   Phase 1 -> arrive(bar0) + pair-sync -> cp.async Q/K -> Phase A + rowsum
//   -> wait(bar0) -> prefix slice -> bar1 -> Mp/V + Np-dot -> Phase B+C
// ============================================================================
__global__ void __launch_bounds__(512, 1)
fused_kernel(const float* __restrict__ K, const float* __restrict__ Q,
             const float* __restrict__ W, const float* __restrict__ V,
             float* __restrict__ out) {
    extern __shared__ char smraw[];
    __shared__ unsigned int s_tgt0;
    const int tid  = threadIdx.x;
    const int lane = tid & 31;
    const int wid  = tid >> 5;
    const int chunk = blockIdx.x >> 1, half = blockIdx.x & 1;
    FRAG_OFFS();

    // ======================= PHASE 1 =======================
    {
        __half* Xs  = (__half*)smraw;              // [128][LDH]
        __half* Ws  = Xs + DD*LDH;                 // [128][LDH]
        __half* Kt2 = Ws + DD*LDH;                 // [128][LD2]
        __half* Vt2 = Kt2 + DD*LD2;                // [128][LD2]
        float*  scale = (float*)(Vt2 + DD*LD2);    // [128]

        const size_t rbase = (size_t)chunk*CC + half*64;
        const float* Kg = K + rbase*DD;
        const float* Qg = Q + rbase*DD;
        const float* Vg = V + rbase*DD;

        if (tid < 128) scale[tid] = 0.f;
        __syncthreads();

        #pragma unroll
        for (int it = 0; it < 8; ++it) {
            int i = tid + it*512;
            int t = i >> 5, d4 = i & 31;
            const float* src = (t < 64) ? (Kg + (size_t)t*DD) : (Qg + (size_t)(t-64)*DD);
            float4 v = reinterpret_cast<const float4*>(src)[d4];
            float ls = v.x*v.x + v.y*v.y + v.z*v.z + v.w*v.w;
            ls += __shfl_xor_sync(~0u, ls, 16);
            ls += __shfl_xor_sync(~0u, ls, 8);
            ls += __shfl_xor_sync(~0u, ls, 4);
            ls += __shfl_xor_sync(~0u, ls, 2);
            ls += __shfl_xor_sync(~0u, ls, 1);
            if (lane == 0) atomicAdd(&scale[t], ls);
            *reinterpret_cast<__half2*>(Xs + t*LDH + d4*4)     = __floats2half2_rn(v.x, v.y);
            *reinterpret_cast<__half2*>(Xs + t*LDH + d4*4 + 2) = __floats2half2_rn(v.z, v.w);
            float4 w = reinterpret_cast<const float4*>(W)[t*32 + d4];
            *reinterpret_cast<__half2*>(Ws + t*LDH + d4*4)     = __floats2half2_rn(w.x, w.y);
            *reinterpret_cast<__half2*>(Ws + t*LDH + d4*4 + 2) = __floats2half2_rn(w.z, w.w);
        }
        __syncthreads();
        if (tid < 128)
            scale[tid] = __expf(-0.5f * sqrtf(scale[tid])) * 0.08838834764831845f;

        float4 vreg[8];
        if (wid >= 8) {
            int q = tid - 256;
            #pragma unroll
            for (int it = 0; it < 8; ++it) {
                int i = q + it*256;
                vreg[it] = reinterpret_cast<const float4*>(Vg)[(size_t)(i & 63)*32 + (i >> 6)];
            }
        }
        __syncthreads();

        const int wm0 = (wid >> 2) * 32;
        const int wn0 = (wid & 3) * 32;
        const uint32_t uX = sptr(Xs), uW = sptr(Ws);
        const uint32_t uK2 = sptr(Kt2), uV2 = sptr(Vt2);

        float acc[2][4][4];
        #pragma unroll
        for (int mi = 0; mi < 2; ++mi)
            #pragma unroll
            for (int ni = 0; ni < 4; ++ni)
                #pragma unroll
                for (int q = 0; q < 4; ++q) acc[mi][ni][q] = 0.f;

        GEMM_PIPE_24(acc, uX, wm0, uW, wn0, LDH, 8);

        __half2 oph[2][4][2];
        #pragma unroll
        for (int mi = 0; mi < 2; ++mi) {
            int r0 = wm0 + mi*16 + er;
            float s0 = scale[r0], s1 = scale[r0 + 8];
            #pragma unroll
            for (int ni = 0; ni < 4; ++ni) {
                oph[mi][ni][0] = __floats2half2_rn(s0*__expf(acc[mi][ni][0]), s0*__expf(acc[mi][ni][1]));
                oph[mi][ni][1] = __floats2half2_rn(s1*__expf(acc[mi][ni][2]), s1*__expf(acc[mi][ni][3]));
            }
        }

        {
            __half* dst = (wm0 < 64) ? g_phiK : g_phiQ;
            int mofs    = (wm0 < 64) ? 0 : 64;
            #pragma unroll
            for (int mi = 0; mi < 2; ++mi) {
                int m = wm0 + mi*16 + er;
                size_t g0 = (rbase + (m - mofs)) * DD;
                #pragma unroll
                for (int ni = 0; ni < 4; ++ni) {
                    int col = wn0 + ni*8 + ec;
                    *reinterpret_cast<__half2*>(dst + g0 + col)        = oph[mi][ni][0];
                    *reinterpret_cast<__half2*>(dst + g0 + 8*DD + col) = oph[mi][ni][1];
                }
            }
        }

        if (wm0 < 64) {
            #pragma unroll
            for (int mi = 0; mi < 2; ++mi) {
                int t0 = wm0 + mi*16 + er;
                #pragma unroll
                for (int ni = 0; ni < 4; ++ni) {
                    int col = wn0 + ni*8 + ec;
                    Kt2[(col  )*LD2 + t0]     = oph[mi][ni][0].x;
                    Kt2[(col+1)*LD2 + t0]     = oph[mi][ni][0].y;
                    Kt2[(col  )*LD2 + t0 + 8] = oph[mi][ni][1].x;
                    Kt2[(col+1)*LD2 + t0 + 8] = oph[mi][ni][1].y;
                }
            }
        } else {
            __half* Vthg = g_Vth + (size_t)chunk*CC*DD + half*64;
            int q = tid - 256;
            #pragma unroll
            for (int it = 0; it < 8; ++it) {
                int i = q + it*256;
                int t = i & 63, d4 = i >> 6;
                float4 v = vreg[it];
                __half h0 = __float2half_rn(v.x), h1 = __float2half_rn(v.y);
                __half h2 = __float2half_rn(v.z), h3 = __float2half_rn(v.w);
                Vt2[(d4*4+0)*LD2 + t] = h0;
                Vt2[(d4*4+1)*LD2 + t] = h1;
                Vt2[(d4*4+2)*LD2 + t] = h2;
                Vt2[(d4*4+3)*LD2 + t] = h3;
                Vthg[(size_t)(d4*4+0)*128 + t] = h0;
                Vthg[(size_t)(d4*4+1)*128 + t] = h1;
                Vthg[(size_t)(d4*4+2)*128 + t] = h2;
                Vthg[(size_t)(d4*4+3)*128 + t] = h3;
            }
        }
        __syncthreads();

        float acc2[2][4][4];
        #pragma unroll
        for (int mi = 0; mi < 2; ++mi)
            #pragma unroll
            for (int ni = 0; ni < 4; ++ni)
                #pragma unroll
                for (int q = 0; q < 4; ++q) acc2[mi][ni][q] = 0.f;

        GEMM_PIPE_24(acc2, uV2, wm0, uK2, wn0, LD2, 4);

        float* Sg = g_ScTp[half] + (size_t)chunk*DD*DD;
        #pragma unroll
        for (int mi = 0; mi < 2; ++mi) {
            int r0 = wm0 + mi*16 + er;
            #pragma unroll
            for (int ni = 0; ni < 4; ++ni) {
                int col = wn0 + ni*8 + ec;
                *reinterpret_cast<float2*>(Sg + (size_t)r0*DD + col)     = make_float2(acc2[mi][ni][0], acc2[mi][ni][1]);
                *reinterpret_cast<float2*>(Sg + (size_t)(r0+8)*DD + col) = make_float2(acc2[mi][ni][2], acc2[mi][ni][3]);
            }
        }

        if (tid < 128) {
            float s = 0.f;
            #pragma unroll 8
            for (int t = 0; t < 64; ++t) s += __half2float(Kt2[tid*LD2 + t]);
            g_ncp[half][(size_t)chunk*DD + tid] = s;
        }
    }

    // ===== arrive(bar0) non-blocking + pairwise sync with partner half =====
    __syncthreads();      // all phase-1 global stores issued
    if (tid == 0) {
        s_tgt0 = bar_arrive(&g_bar[0], NBLK);
        unsigned int ptgt = bar_arrive(&g_pair[chunk], 2u);
        bar_wait(&g_pair[chunk], ptgt);
    }
    __syncthreads();      // partner's phi / Vth now visible

    // phase-3 smem views (alias phase-1 regions, now dead)
    __half* Qs = (__half*)smraw;         // [128][LDH]
    __half* Bs = Qs + DD*LDH;            // [128][LDH]
    __half* As = Bs + DD*LDH;            // [128][LDH]
    __half* Ms = As + DD*LDH;            // [64][LDH]
    __half* Vs = Ms + 64*LDH;            // [64][LDH]
    float*  rs = (float*)(Vs + 64*LDH);  // [128]
    float*  Np = rs + 128;               // [128]
    const uint32_t uQ = sptr(Qs), uB = sptr(Bs), uA = sptr(As);
    const uint32_t uM = sptr(Ms), uV = sptr(Vs);

    const int j0h = half * 64;
    const __half* Qg3 = g_phiQ + (size_t)chunk*CC*DD;
    const __half* Kg3 = g_phiK + (size_t)chunk*CC*DD;
    const __half* Mg3 = g_MpTh + (size_t)chunk*DD*DD + (size_t)j0h*DD;
    const __half* Vg3 = g_Vth  + (size_t)chunk*CC*DD + (size_t)j0h*DD;

    // Q + K tiles (partner data ready via pair sync)
    #pragma unroll
    for (int it = 0; it < 4; ++it) {
        int i = tid + it*512;
        int t = i >> 4, c8 = i & 15;
        CP_ASYNC16(uQ + t*(LDH*2) + c8*16, Qg3 + t*128 + c8*8);
        CP_ASYNC16(uB + t*(LDH*2) + c8*16, Kg3 + t*128 + c8*8);
    }
    CP_COMMIT();

    if (tid < 128) rs[tid] = 0.f;
    CP_WAIT(0);
    __syncthreads();

    // ======================= PHASE A + rowsum =======================
    const int wm0 = (wid >> 2) * 32;
    {
        const int wn0 = (wid & 3) * 32;
        float acc[2][4][4];
        #pragma unroll
        for (int mi = 0; mi < 2; ++mi)
            #pragma unroll
            for (int ni = 0; ni < 4; ++ni)
                #pragma unroll
                for (int q = 0; q < 4; ++q) acc[mi][ni][q] = 0.f;

        GEMM_PIPE_24(acc, uQ, wm0, uB, wn0, LDH, 8);

        #pragma unroll
        for (int mi = 0; mi < 2; ++mi) {
            int t0 = wm0 + mi*16 + er;
            int t1 = t0 + 8;
            #pragma unroll
            for (int ni = 0; ni < 4; ++ni) {
                int s0 = wn0 + ni*8 + ec;
                float v0 = (s0     <= t0) ? acc[mi][ni][0] : 0.f;
                float v1 = (s0 + 1 <= t0) ? acc[mi][ni][1] : 0.f;
                float v2 = (s0     <= t1) ? acc[mi][ni][2] : 0.f;
                float v3 = (s0 + 1 <= t1) ? acc[mi][ni][3] : 0.f;
                *reinterpret_cast<__half2*>(As + t0*LDH + s0) = __floats2half2_rn(v0, v1);
                *reinterpret_cast<__half2*>(As + t1*LDH + s0) = __floats2half2_rn(v2, v3);
            }
        }
    }
    __syncthreads();

    // rowsum(A) part of denominators
    {
        int t = tid & 127, p = tid >> 7;
        float r = 0.f;
        const int s0 = p * 32;
        #pragma unroll 8
        for (int s = s0; s < s0 + 32; s += 2) {
            float2 f = __half22float2(*reinterpret_cast<__half2*>(As + t*LDH + s));
            r += f.x + f.y;
        }
        atomicAdd(&rs[t], r);
    }

    // ===== wait(bar0): all ScTp/ncp visible (mostly elapsed under phase A) =====
    if (tid == 0) bar_wait(&g_bar[0], s_tgt0);
    __syncthreads();

    // ======================= PHASE 2: prefix slice =======================
    {
        int gtid = blockIdx.x*512 + tid;          // 0..65535, one e-column each
        int bb = gtid >> 14;
        int e0 = gtid & 16383;
        const size_t base = (size_t)bb*NCH*DD*DD + e0;
        float a = 0.f;
        #pragma unroll
        for (int c = 0; c < NCH; ++c) {
            size_t off = base + (size_t)c*DD*DD;
            g_MpTh[off] = __float2half_rn(a);
            a += g_ScTp[0][off] + g_ScTp[1][off];
        }
        if (gtid < 512) {
            int b2 = gtid >> 7, i2 = gtid & 127;
            float an = 0.f;
            #pragma unroll
            for (int c = 0; c < NCH; ++c) {
                size_t off = (size_t)(b2*NCH + c)*DD + i2;
                g_Np[off] = an;
                an += g_ncp[0][off] + g_ncp[1][off];
            }
        }
    }

    // ===== bar1: MpTh / Np globally visible =====
    __syncthreads();
    if (tid == 0) {
        unsigned int tgt = bar_arrive(&g_bar[1], NBLK);
        bar_wait(&g_bar[1], tgt);
    }
    __syncthreads();

    // Mp + V^T tiles
    #pragma unroll
    for (int it = 0; it < 2; ++it) {
        int i = tid + it*512;
        int e = i >> 4, c8 = i & 15;
        CP_ASYNC16(uM + e*(LDH*2) + c8*16, Mg3 + e*128 + c8*8);
        CP_ASYNC16(uV + e*(LDH*2) + c8*16, Vg3 + e*128 + c8*8);
    }
    CP_COMMIT();

    if (tid < 128) Np[tid] = g_Np[(size_t)chunk*DD + tid];
    __syncthreads();

    // Np-dot part of denominators
    {
        int t = tid & 127, p = tid >> 7;
        float r = 0.f;
        const int d0 = p * 32;
        #pragma unroll 8
        for (int d = d0; d < d0 + 32; ++d)
            r = fmaf(__half2float(Qs[t*LDH + d]), Np[d], r);
        atomicAdd(&rs[t], r);
    }
    CP_WAIT(0);
    __syncthreads();

    // ======================= PHASE B+C =======================
    {
        const int wn0 = (wid & 3) * 16;
        float acc[2][2][4];
        #pragma unroll
        for (int mi = 0; mi < 2; ++mi)
            #pragma unroll
            for (int ni = 0; ni < 2; ++ni)
                #pragma unroll
                for (int q = 0; q < 4; ++q) acc[mi][ni][q] = 0.f;

        uint32_t a_[2][2][4]; uint32_t b_[2][4];
        LOADA2_S(a_[0], uQ, wm0, 0, LDH);
        LOADB16_S(b_[0], uM, wn0, 0, LDH);
        #pragma unroll
        for (int kk = 0; kk < 16; ++kk) {
            const int cur = kk & 1, nxt = cur ^ 1;
            const int k1 = kk + 1;
            if (k1 < 8) {
                LOADA2_S(a_[nxt], uQ, wm0, k1*16, LDH);
                LOADB16_S(b_[nxt], uM, wn0, k1*16, LDH);
            } else if (k1 < 16) {
                LOADA2_S(a_[nxt], uA, wm0, (k1-8)*16, LDH);
                LOADB16_S(b_[nxt], uV, wn0, (k1-8)*16, LDH);
            }
            #pragma unroll
            for (int mi = 0; mi < 2; ++mi)
                #pragma unroll
                for (int ni = 0; ni < 2; ++ni)
                    MMA16(acc[mi][ni], a_[cur][mi], b_[cur][2*ni], b_[cur][2*ni+1]);
        }

        #pragma unroll
        for (int mi = 0; mi < 2; ++mi) {
            int t0 = wm0 + mi*16 + er;
            float r0 = rs[t0];
            float inv0 = 1.f / (r0 + (r0 > 0.f ? 1e-6f : (r0 < 0.f ? -1e-6f : 0.f)));
            float r1 = rs[t0 + 8];
            float inv1 = 1.f / (r1 + (r1 > 0.f ? 1e-6f : (r1 < 0.f ? -1e-6f : 0.f)));
            size_t row0 = (size_t)chunk*CC + t0;
            #pragma unroll
            for (int ni = 0; ni < 2; ++ni) {
                int col = j0h + wn0 + ni*8 + ec;
                *reinterpret_cast<float2*>(out + row0*DD + col) =
                    make_float2(acc[mi][ni][0]*inv0, acc[mi][ni][1]*inv0);
                *reinterpret_cast<float2*>(out + (row0 + 8)*DD + col) =
                    make_float2(acc[mi][ni][2]*inv1, acc[mi][ni][3]*inv1);
            }
        }
    }
}

// ============================================================================
extern "C" void kernel_launch(void* const* d_in, const int* in_sizes, int n_in,
                              void* d_out, int out_size) {
    const float* K = (const float*)d_in[0];
    const float* Q = (const float*)d_in[1];
    const float* V = (const float*)d_in[2];
    const float* W = (const float*)d_in[6];
    float* out = (float*)d_out;

    const int SMEM = (3*DD + 2*64)*LDH*2 + 1024;   // ~141 KB

    cudaFuncSetAttribute(fused_kernel, cudaFuncAttributeMaxDynamicSharedMemorySize, SMEM);
    fused_kernel<<<NBLK, 512, SMEM>>>(K, Q, W, V, out);
}